// round 1
// baseline (speedup 1.0000x reference)
#include <cuda_runtime.h>
#include <math.h>
#include <float.h>

#define N 256
#define DIM 128

// Deterministic per-block partials (no float atomics -> bitwise deterministic).
__device__ float g_partial_sum[N];
__device__ float g_partial_cnt[N];

__global__ void triplet_main(const float* __restrict__ emb,
                             const int* __restrict__ lab32) {
    __shared__ float4 sh_e[DIM / 4];
    __shared__ float d_row[N];
    __shared__ int   sh_lab[N];
    __shared__ float negd[N];
    __shared__ int   negcnt;
    __shared__ int   any_odd_nonzero;
    __shared__ float rs[N], rc[N];

    const int i = blockIdx.x;
    const int t = threadIdx.x;

    if (t == 0) { negcnt = 0; any_odd_nonzero = 0; }
    __syncthreads();

    // --- label dtype sniff: int64 little-endian (values 0..15) has all-zero
    // odd 32-bit words; genuine int32 labels won't (prob 16^-128).
    // Reading lab32[0..255] is in-bounds for BOTH layouts (>=1024 bytes).
    if (t < 128) {
        if (lab32[2 * t + 1] != 0) atomicOr(&any_odd_nonzero, 1);
    }
    if (t < DIM / 4)
        sh_e[t] = reinterpret_cast<const float4*>(emb + (size_t)i * DIM)[t];
    __syncthreads();

    const bool is64 = (any_odd_nonzero == 0);
    sh_lab[t] = is64 ? lab32[2 * t] : lab32[t];
    __syncthreads();

    // --- d[i][t] = sqrt(max(|e_i|^2 + |e_t|^2 - 2<e_i,e_t>, EPS))
    const float4* ej = reinterpret_cast<const float4*>(emb + (size_t)t * DIM);
    float dot = 0.f, nj = 0.f, ni = 0.f;
#pragma unroll
    for (int c = 0; c < DIM / 4; ++c) {
        float4 a = sh_e[c];
        float4 b = ej[c];
        dot += a.x * b.x + a.y * b.y + a.z * b.z + a.w * b.w;
        nj  += b.x * b.x + b.y * b.y + b.z * b.z + b.w * b.w;
        ni  += a.x * a.x + a.y * a.y + a.z * a.z + a.w * a.w;
    }
    float dist = sqrtf(fmaxf(ni + nj - 2.f * dot, 1e-4f));
    d_row[t] = dist;

    // pos[i,t] = (labels equal) && (t != i).  Negatives = !pos (includes t==i,
    // matching the reference's (1 - pos) factor in M).
    const bool is_pos = (sh_lab[t] == sh_lab[i]) && (t != i);
    if (!is_pos) {
        int idx = atomicAdd(&negcnt, 1);
        negd[idx] = dist;     // order irrelevant: only fed to min/max
    }
    __syncthreads();

    float lsum = 0.f, lcnt = 0.f;
    if (is_pos) {
        const float D = d_row[t];
        float minAbove = FLT_MAX;
        float maxNeg   = -FLT_MAX;
        const int m = negcnt;
        for (int j = 0; j < m; ++j) {
            float dj = negd[j];
            maxNeg = fmaxf(maxNeg, dj);
            if (dj > D) minAbove = fminf(minAbove, dj);  // strict: dist_diff < 0
        }
        float semi = (minAbove < FLT_MAX) ? (D - minAbove)   // semi-hard exists
                                          : (D - maxNeg);    // easiest-negative fallback
        lsum = fmaxf(semi + 1.0f, 0.f);   // relu(semi + MARGIN)
        lcnt = 1.f;
    }

    // deterministic block tree reduction
    rs[t] = lsum; rc[t] = lcnt;
    __syncthreads();
#pragma unroll
    for (int s = N / 2; s > 0; s >>= 1) {
        if (t < s) { rs[t] += rs[t + s]; rc[t] += rc[t + s]; }
        __syncthreads();
    }
    if (t == 0) { g_partial_sum[i] = rs[0]; g_partial_cnt[i] = rc[0]; }
}

__global__ void triplet_final(float* __restrict__ out) {
    __shared__ float rs[N], rc[N];
    const int t = threadIdx.x;
    rs[t] = g_partial_sum[t];
    rc[t] = g_partial_cnt[t];
    __syncthreads();
#pragma unroll
    for (int s = N / 2; s > 0; s >>= 1) {
        if (t < s) { rs[t] += rs[t + s]; rc[t] += rc[t + s]; }
        __syncthreads();
    }
    if (t == 0) out[0] = rs[0] / rc[0];
}

extern "C" void kernel_launch(void* const* d_in, const int* in_sizes, int n_in,
                              void* d_out, int out_size) {
    const float* emb  = (const float*)d_in[0];
    const int*   labs = (const int*)d_in[1];   // int32 or int64 (sniffed in-kernel)
    float* out = (float*)d_out;

    triplet_main<<<N, N>>>(emb, labs);
    triplet_final<<<1, N>>>(out);
}

// round 2
// speedup vs baseline: 1.0398x; 1.0398x over previous
#include <cuda_runtime.h>
#include <math.h>
#include <float.h>

#define N 256
#define DIM 128

// Deterministic per-block partials + ticket for single-kernel fusion.
__device__ float g_psum[N];
__device__ float g_pcnt[N];
__device__ unsigned int g_ticket = 0;   // reset by last block each launch

__global__ void __launch_bounds__(N, 2)
triplet_fused(const float* __restrict__ emb,
              const int*   __restrict__ lab32,
              float*       __restrict__ out) {
    __shared__ float4 sh_e[DIM / 4];
    __shared__ float  negd[N];
    __shared__ float  wsum[8], wcnt[8];
    __shared__ int    sh_flag;   // label dtype sniff
    __shared__ int    sh_last;   // am I the last block?

    const int i = blockIdx.x;
    const int t = threadIdx.x;
    const int w = t >> 5, l = t & 31;

    if (t == 0) { sh_flag = 0; sh_last = 0; }
    __syncthreads();

    // int64 little-endian labels (0..15) have all-zero odd 32-bit words.
    // Reading word [0..255] is in-bounds for both int32 and int64 layouts.
    if (t < 128 && lab32[2 * t + 1] != 0) sh_flag = 1;
    if (t < DIM / 4)
        sh_e[t] = reinterpret_cast<const float4*>(emb + (size_t)i * DIM)[t];
    __syncthreads();

    const bool is64 = (sh_flag == 0);
    const int  labI = is64 ? lab32[2 * i] : lab32[i];
    const int  labT = is64 ? lab32[2 * t] : lab32[t];
    const bool is_pos = (labT == labI) && (t != i);

    // d[i][t] = sqrt(max(|e_i|^2 + |e_t|^2 - 2<e_i,e_t>, EPS))
    const float4* ej = reinterpret_cast<const float4*>(emb + (size_t)t * DIM);
    float dot = 0.f, ni = 0.f, nj = 0.f;
#pragma unroll
    for (int c = 0; c < DIM / 4; ++c) {
        float4 a = sh_e[c];
        float4 b = ej[c];
        dot += a.x * b.x + a.y * b.y + a.z * b.z + a.w * b.w;
        ni  += a.x * a.x + a.y * a.y + a.z * a.z + a.w * a.w;
        nj  += b.x * b.x + b.y * b.y + b.z * b.z + b.w * b.w;
    }
    const float D = sqrtf(fmaxf(ni + nj - 2.f * dot, 1e-4f));

    // Negatives (incl. t==i, matching reference's (1-pos) with no eye subtraction
    // on that factor). Positives masked with -FLT_MAX: never the max, never > D.
    negd[t] = is_pos ? -FLT_MAX : D;
    __syncthreads();

    float lsum = 0.f, lcnt = 0.f;
    if (is_pos) {
        float mx0 = -FLT_MAX, mx1 = -FLT_MAX, mx2 = -FLT_MAX, mx3 = -FLT_MAX;
        float mn0 =  FLT_MAX, mn1 =  FLT_MAX, mn2 =  FLT_MAX, mn3 =  FLT_MAX;
#pragma unroll
        for (int j = 0; j < N; j += 4) {
            float d0 = negd[j + 0], d1 = negd[j + 1];
            float d2 = negd[j + 2], d3 = negd[j + 3];
            mx0 = fmaxf(mx0, d0); mx1 = fmaxf(mx1, d1);
            mx2 = fmaxf(mx2, d2); mx3 = fmaxf(mx3, d3);
            mn0 = fminf(mn0, d0 > D ? d0 : FLT_MAX);
            mn1 = fminf(mn1, d1 > D ? d1 : FLT_MAX);
            mn2 = fminf(mn2, d2 > D ? d2 : FLT_MAX);
            mn3 = fminf(mn3, d3 > D ? d3 : FLT_MAX);
        }
        float mx = fmaxf(fmaxf(mx0, mx1), fmaxf(mx2, mx3));
        float mn = fminf(fminf(mn0, mn1), fminf(mn2, mn3));
        // semi-hard if any negative strictly farther than D, else easiest negative
        float semi = (mn < FLT_MAX) ? (D - mn) : (D - mx);
        lsum = fmaxf(semi + 1.0f, 0.f);   // relu(semi + MARGIN)
        lcnt = 1.f;
    }

    // warp-shuffle reduction, then 8 warp partials
#pragma unroll
    for (int s = 16; s > 0; s >>= 1) {
        lsum += __shfl_down_sync(0xffffffffu, lsum, s);
        lcnt += __shfl_down_sync(0xffffffffu, lcnt, s);
    }
    if (l == 0) { wsum[w] = lsum; wcnt[w] = lcnt; }
    __syncthreads();

    if (t == 0) {
        float s = 0.f, c = 0.f;
#pragma unroll
        for (int k = 0; k < 8; ++k) { s += wsum[k]; c += wcnt[k]; }
        g_psum[i] = s;
        g_pcnt[i] = c;
        __threadfence();
        unsigned tk = atomicAdd(&g_ticket, 1u);
        if (tk == N - 1) {
            sh_last  = 1;
            g_ticket = 0;   // reset for next graph replay (all blocks done adding)
        }
    }
    __syncthreads();

    // Last block: final reduction over all 256 per-row partials.
    // Safe: this SM never read g_psum earlier this launch and L1 is flushed
    // per launch, so writer threadfence + L2 gives correct values.
    if (sh_last) {
        float s = g_psum[t];
        float c = g_pcnt[t];
#pragma unroll
        for (int sft = 16; sft > 0; sft >>= 1) {
            s += __shfl_down_sync(0xffffffffu, s, sft);
            c += __shfl_down_sync(0xffffffffu, c, sft);
        }
        if (l == 0) { wsum[w] = s; wcnt[w] = c; }
        __syncthreads();
        if (t == 0) {
            float S = 0.f, C = 0.f;
#pragma unroll
            for (int k = 0; k < 8; ++k) { S += wsum[k]; C += wcnt[k]; }
            out[0] = S / C;
        }
    }
}

extern "C" void kernel_launch(void* const* d_in, const int* in_sizes, int n_in,
                              void* d_out, int out_size) {
    const float* emb  = (const float*)d_in[0];
    const int*   labs = (const int*)d_in[1];
    float* out = (float*)d_out;
    triplet_fused<<<N, N>>>(emb, labs, out);
}

// round 3
// speedup vs baseline: 1.5437x; 1.4846x over previous
#include <cuda_runtime.h>
#include <math.h>
#include <float.h>

#define N 256
#define DIM 128
#define PADJ 17   // float2 stride per partial row (conflict-free)

__device__ float g_psum[N];
__device__ float g_pcnt[N];
__device__ unsigned int g_ticket = 0;   // reset by last block each launch

__global__ void __launch_bounds__(N, 2)
triplet_fused(const float* __restrict__ emb,
              const int*   __restrict__ lab32,
              float*       __restrict__ out) {
    __shared__ float2 part[N * PADJ];     // 34816 B: 16 (dot,norm) partials per row
    __shared__ float4 sh_e[DIM / 4];      // row i of E
    __shared__ float  negd[N];
    __shared__ float  wsum[8], wcnt[8];
    __shared__ float  sh_ni;
    __shared__ int    sh_flag, sh_last;

    const int i = blockIdx.x;
    const int t = threadIdx.x;
    const int w = t >> 5, l = t & 31;

    if (t == 0) { sh_flag = 0; sh_last = 0; }
    __syncthreads();

    // int64 LE labels (0..15) have all-zero odd 32-bit words; int32 labels don't.
    // Words [0..255] are in-bounds for both layouts.
    if (t < 128 && lab32[2 * t + 1] != 0) sh_flag = 1;
    if (t < DIM / 4)
        sh_e[t] = reinterpret_cast<const float4*>(emb + (size_t)i * DIM)[t];
    __syncthreads();

    const bool is64 = (sh_flag == 0);
    const int  labI = is64 ? lab32[2 * i] : lab32[i];
    const int  labT = is64 ? lab32[2 * t] : lab32[t];
    const bool is_pos = (labT == labI) && (t != i);

    // ---- Phase 1: coalesced split-K partial dots.
    // Warp w owns rows [w*32, w*32+32). Lane l loads E4[j*32+l]: 512B contiguous
    // per row = 4 L1 wavefronts (minimum). Fold lanes 16..31 into 0..15 by shuffle.
    {
        const float4  a  = sh_e[l];
        const float4* E4 = reinterpret_cast<const float4*>(emb);
        const int jbase = w * 32;
#pragma unroll 4
        for (int jj = 0; jj < 32; ++jj) {
            const int j = jbase + jj;
            float4 b = E4[j * 32 + l];
            float dp = b.x * a.x + b.y * a.y + b.z * a.z + b.w * a.w;
            float np = b.x * b.x + b.y * b.y + b.z * b.z + b.w * b.w;
            dp += __shfl_down_sync(0xffffffffu, dp, 16);
            np += __shfl_down_sync(0xffffffffu, np, 16);
            if (l < 16) part[j * PADJ + l] = make_float2(dp, np);
        }
    }
    __syncthreads();

    // ---- Phase 2: thread t folds its 16 partials -> dot(e_i,e_t), |e_t|^2
    float dot, nt;
    {
        float d0 = 0.f, d1 = 0.f, n0 = 0.f, n1 = 0.f;
        const float2* p = &part[t * PADJ];
#pragma unroll
        for (int c = 0; c < 16; c += 2) {
            float2 x = p[c], y = p[c + 1];
            d0 += x.x; n0 += x.y;
            d1 += y.x; n1 += y.y;
        }
        dot = d0 + d1;
        nt  = n0 + n1;
    }
    if (t == i) sh_ni = nt;
    __syncthreads();

    const float D = sqrtf(fmaxf(sh_ni + nt - 2.f * dot, 1e-4f));
    // Negatives include t==i (reference's (1-pos) keeps the diagonal, d_ii=0.01).
    negd[t] = is_pos ? -FLT_MAX : D;
    __syncthreads();

    // ---- Phase 3: per-positive scan (vectorized, broadcast LDS)
    float lsum = 0.f, lcnt = 0.f;
    if (is_pos) {
        const float4* nd = reinterpret_cast<const float4*>(negd);
        float mx0 = -FLT_MAX, mx1 = -FLT_MAX;
        float mn0 =  FLT_MAX, mn1 =  FLT_MAX;
#pragma unroll 8
        for (int j = 0; j < N / 4; j += 2) {
            float4 v = nd[j], u = nd[j + 1];
            mx0 = fmaxf(mx0, fmaxf(fmaxf(v.x, v.y), fmaxf(v.z, v.w)));
            mx1 = fmaxf(mx1, fmaxf(fmaxf(u.x, u.y), fmaxf(u.z, u.w)));
            mn0 = fminf(mn0, v.x > D ? v.x : FLT_MAX);
            mn1 = fminf(mn1, v.y > D ? v.y : FLT_MAX);
            mn0 = fminf(mn0, v.z > D ? v.z : FLT_MAX);
            mn1 = fminf(mn1, v.w > D ? v.w : FLT_MAX);
            mn0 = fminf(mn0, u.x > D ? u.x : FLT_MAX);
            mn1 = fminf(mn1, u.y > D ? u.y : FLT_MAX);
            mn0 = fminf(mn0, u.z > D ? u.z : FLT_MAX);
            mn1 = fminf(mn1, u.w > D ? u.w : FLT_MAX);
        }
        float mx = fmaxf(mx0, mx1);
        float mn = fminf(mn0, mn1);
        // semi-hard if a strictly-farther negative exists, else easiest negative
        float semi = (mn < FLT_MAX) ? (D - mn) : (D - mx);
        lsum = fmaxf(semi + 1.0f, 0.f);   // relu(semi + MARGIN)
        lcnt = 1.f;
    }

    // ---- block reduction: warp shuffle + 8 partials
#pragma unroll
    for (int s = 16; s > 0; s >>= 1) {
        lsum += __shfl_down_sync(0xffffffffu, lsum, s);
        lcnt += __shfl_down_sync(0xffffffffu, lcnt, s);
    }
    if (l == 0) { wsum[w] = lsum; wcnt[w] = lcnt; }
    __syncthreads();

    if (t == 0) {
        float s = 0.f, c = 0.f;
#pragma unroll
        for (int k = 0; k < 8; ++k) { s += wsum[k]; c += wcnt[k]; }
        g_psum[i] = s;
        g_pcnt[i] = c;
        __threadfence();
        unsigned tk = atomicAdd(&g_ticket, 1u);
        if (tk == N - 1) {
            sh_last  = 1;
            g_ticket = 0;   // safe: all blocks already added
        }
    }
    __syncthreads();

    // ---- last block finishes: reduce the 256 per-row partials (L1-bypass reads)
    if (sh_last) {
        float s = __ldcg(&g_psum[t]);
        float c = __ldcg(&g_pcnt[t]);
#pragma unroll
        for (int sft = 16; sft > 0; sft >>= 1) {
            s += __shfl_down_sync(0xffffffffu, s, sft);
            c += __shfl_down_sync(0xffffffffu, c, sft);
        }
        if (l == 0) { wsum[w] = s; wcnt[w] = c; }
        __syncthreads();
        if (t == 0) {
            float S = 0.f, C = 0.f;
#pragma unroll
            for (int k = 0; k < 8; ++k) { S += wsum[k]; C += wcnt[k]; }
            out[0] = S / C;
        }
    }
}

extern "C" void kernel_launch(void* const* d_in, const int* in_sizes, int n_in,
                              void* d_out, int out_size) {
    const float* emb  = (const float*)d_in[0];
    const int*   labs = (const int*)d_in[1];
    float* out = (float*)d_out;
    triplet_fused<<<N, N>>>(emb, labs, out);
}